// round 1
// baseline (speedup 1.0000x reference)
#include <cuda_runtime.h>
#include <cuda_bf16.h>
#include <math.h>

// ---------------- Problem dims (fixed by setup_inputs) ----------------
#define NL    8
#define BSZ   8
#define LSEQ  1024
#define DM    256
#define DI    512
#define NST   16
#define DTR   16
#define PROJC 48          // dt_rank + 2*N
#define MROWS (BSZ*LSEQ)  // 8192

// ---------------- Device scratch (no allocations allowed) ----------------
__device__ float g_h   [MROWS*DM];        // residual stream (8 MB)
__device__ float g_xz  [MROWS*2*DI];      // in_proj output  (32 MB)
__device__ float g_u   [MROWS*DI];        // conv+silu out   (16 MB)
__device__ float g_proj[MROWS*PROJC];     // x_proj out
__device__ float g_dt  [MROWS*DI];        // softplus(dt)    (16 MB)
__device__ float g_ymod[MROWS*DI];        // y*silu(z)       (16 MB)
__device__ float g_out2[MROWS*DM];        // out_proj out    (8 MB)
__device__ float g_pooled[BSZ*DM];

// ---------------- Encoder: h[b,l,m] = sum_c x[b,c,l]*W[c,m] + b[m] ----------------
__global__ void enc_kernel(const float* __restrict__ x,
                           const float* __restrict__ w,
                           const float* __restrict__ bb) {
    int bl = blockIdx.x;            // 0..8191
    int m  = threadIdx.x;           // 0..255
    int b = bl >> 10, l = bl & 1023;
    float acc = bb[m];
#pragma unroll
    for (int c = 0; c < 3; c++)
        acc = fmaf(x[(b*3 + c)*LSEQ + l], w[c*DM + m], acc);
    g_h[bl*DM + m] = acc;
}

// ---------------- Generic fp32 tiled GEMM: C[MxN] = A[MxK] @ B[KxN] ----------------
// M multiple of 64, K multiple of 16, N guarded.
#define GBM 64
#define GBN 64
#define GBK 16
__global__ void gemm64(const float* __restrict__ A,
                       const float* __restrict__ B,
                       float* __restrict__ C,
                       int M, int N, int K) {
    __shared__ float As[GBK][GBM + 1];
    __shared__ float Bs[GBK][GBN];

    int tid = threadIdx.x;          // 256 threads
    int tx = tid & 15;              // N direction (16)
    int ty = tid >> 4;              // M direction (16)
    int m0 = blockIdx.y * GBM;
    int n0 = blockIdx.x * GBN;

    float acc[4][4] = {};

    for (int k0 = 0; k0 < K; k0 += GBK) {
        // A tile: 64 rows x 16 k, transposed into As[k][m]
#pragma unroll
        for (int i = tid; i < GBM*GBK; i += 256) {
            int m = i >> 4;
            int k = i & 15;
            As[k][m] = A[(size_t)(m0 + m)*K + k0 + k];
        }
        // B tile: 16 k x 64 n
#pragma unroll
        for (int i = tid; i < GBK*GBN; i += 256) {
            int k = i >> 6;
            int n = i & 63;
            Bs[k][n] = (n0 + n < N) ? B[(size_t)(k0 + k)*N + n0 + n] : 0.f;
        }
        __syncthreads();
#pragma unroll
        for (int k = 0; k < GBK; k++) {
            float a0 = As[k][ty*4+0], a1 = As[k][ty*4+1];
            float a2 = As[k][ty*4+2], a3 = As[k][ty*4+3];
            float b0 = Bs[k][tx*4+0], b1 = Bs[k][tx*4+1];
            float b2 = Bs[k][tx*4+2], b3 = Bs[k][tx*4+3];
            acc[0][0] = fmaf(a0,b0,acc[0][0]); acc[0][1] = fmaf(a0,b1,acc[0][1]);
            acc[0][2] = fmaf(a0,b2,acc[0][2]); acc[0][3] = fmaf(a0,b3,acc[0][3]);
            acc[1][0] = fmaf(a1,b0,acc[1][0]); acc[1][1] = fmaf(a1,b1,acc[1][1]);
            acc[1][2] = fmaf(a1,b2,acc[1][2]); acc[1][3] = fmaf(a1,b3,acc[1][3]);
            acc[2][0] = fmaf(a2,b0,acc[2][0]); acc[2][1] = fmaf(a2,b1,acc[2][1]);
            acc[2][2] = fmaf(a2,b2,acc[2][2]); acc[2][3] = fmaf(a2,b3,acc[2][3]);
            acc[3][0] = fmaf(a3,b0,acc[3][0]); acc[3][1] = fmaf(a3,b1,acc[3][1]);
            acc[3][2] = fmaf(a3,b2,acc[3][2]); acc[3][3] = fmaf(a3,b3,acc[3][3]);
        }
        __syncthreads();
    }

#pragma unroll
    for (int tm = 0; tm < 4; tm++) {
        int m = m0 + ty*4 + tm;
#pragma unroll
        for (int tn = 0; tn < 4; tn++) {
            int n = n0 + tx*4 + tn;
            if (n < N) C[(size_t)m*N + n] = acc[tm][tn];
        }
    }
}

// ---------------- Causal depthwise conv (K=4) + SiLU ----------------
__global__ void conv_silu_kernel(const float* __restrict__ cw,
                                 const float* __restrict__ cb) {
    int bl = blockIdx.x;
    int d  = threadIdx.x;           // 0..511
    int b = bl >> 10, l = bl & 1023;
    float acc = cb[d];
#pragma unroll
    for (int k = 0; k < 4; k++) {
        int ll = l + k - 3;
        if (ll >= 0)
            acc = fmaf(g_xz[(size_t)((b << 10) + ll)*(2*DI) + d], cw[d*4 + k], acc);
    }
    float s = acc / (1.f + __expf(-acc));   // silu
    g_u[(size_t)bl*DI + d] = s;
}

// ---------------- dt = softplus(proj[:, :16] @ dt_w + dt_b) ----------------
__global__ void dt_kernel(const float* __restrict__ dtw,
                          const float* __restrict__ dtb) {
    __shared__ float sp[DTR];
    int bl = blockIdx.x;
    int d  = threadIdx.x;           // 0..511
    if (d < DTR) sp[d] = g_proj[bl*PROJC + d];
    __syncthreads();
    float acc = dtb[d];
#pragma unroll
    for (int r = 0; r < DTR; r++)
        acc = fmaf(sp[r], dtw[r*DI + d], acc);
    // softplus
    g_dt[(size_t)bl*DI + d] = (acc > 20.f) ? acc : log1pf(__expf(acc));
}

// ---------------- Selective scan + gate: ymod = (scan(u,dt,B,C)+u*D)*silu(z) --------
// One 16-lane half-warp per (b,d) channel; lane n holds state[n].
__global__ void scan_kernel(const float* __restrict__ A_log,
                            const float* __restrict__ Dv) {
    int gtid = blockIdx.x * blockDim.x + threadIdx.x;
    int gw   = gtid >> 5;
    int lane = threadIdx.x & 31;
    int ch = gw*2 + (lane >> 4);    // 0..4095
    int n  = lane & 15;
    int b = ch >> 9;
    int d = ch & 511;

    float Ad = -__expf(A_log[d*NST + n]);
    float Dd = Dv[d];
    float state = 0.f;
    int blbase = b << 10;

#pragma unroll 4
    for (int l = 0; l < LSEQ; l++) {
        int bl = blbase + l;
        float dtv = g_dt[(size_t)bl*DI + d];
        float uv  = g_u [(size_t)bl*DI + d];
        float Bv  = g_proj[bl*PROJC + DTR + n];
        float Cv  = g_proj[bl*PROJC + DTR + NST + n];
        state = fmaf(__expf(dtv*Ad), state, dtv*uv*Bv);
        float p = state * Cv;
        p += __shfl_xor_sync(0xffffffffu, p, 8);
        p += __shfl_xor_sync(0xffffffffu, p, 4);
        p += __shfl_xor_sync(0xffffffffu, p, 2);
        p += __shfl_xor_sync(0xffffffffu, p, 1);
        if (n == 0) {
            float zv = g_xz[(size_t)bl*(2*DI) + DI + d];
            float sz = zv / (1.f + __expf(-zv));
            g_ymod[(size_t)bl*DI + d] = (p + uv*Dd) * sz;
        }
    }
}

// ---------------- Residual add + LayerNorm (in-place into g_h) ----------------
__global__ void ln_kernel(const float* __restrict__ gamma,
                          const float* __restrict__ beta) {
    __shared__ float s1[8], s2[8];
    int bl = blockIdx.x;
    int m  = threadIdx.x;           // 0..255
    float t = g_out2[bl*DM + m] + g_h[bl*DM + m];
    float v1 = t, v2 = t*t;
#pragma unroll
    for (int o = 16; o > 0; o >>= 1) {
        v1 += __shfl_xor_sync(0xffffffffu, v1, o);
        v2 += __shfl_xor_sync(0xffffffffu, v2, o);
    }
    if ((m & 31) == 0) { s1[m >> 5] = v1; s2[m >> 5] = v2; }
    __syncthreads();
    float sum = 0.f, sq = 0.f;
#pragma unroll
    for (int i = 0; i < 8; i++) { sum += s1[i]; sq += s2[i]; }
    float mean = sum * (1.f/DM);
    float var  = sq * (1.f/DM) - mean*mean;
    float r = rsqrtf(var + 1e-5f);
    g_h[bl*DM + m] = (t - mean) * r * gamma[m] + beta[m];
}

// ---------------- Mean pool over L ----------------
__global__ void pool_kernel() {
    int b = blockIdx.x;             // 0..7
    int m = threadIdx.x;            // 0..255
    float s = 0.f;
    for (int l = 0; l < LSEQ; l++)
        s += g_h[(size_t)((b << 10) + l)*DM + m];
    g_pooled[b*DM + m] = s * (1.f/LSEQ);
}

// ---------------- Decoder: out[b,o] = pooled[b] @ dec_w + dec_b ----------------
__global__ void dec_kernel(const float* __restrict__ w,
                           const float* __restrict__ bb,
                           float* __restrict__ out) {
    int i = threadIdx.x;
    if (i < BSZ*10) {
        int b = i / 10, o = i % 10;
        float acc = bb[o];
#pragma unroll 8
        for (int m = 0; m < DM; m++)
            acc = fmaf(g_pooled[b*DM + m], w[m*10 + o], acc);
        out[i] = acc;
    }
}

// ---------------- Launch ----------------
extern "C" void kernel_launch(void* const* d_in, const int* in_sizes, int n_in,
                              void* d_out, int out_size) {
    const float* x         = (const float*)d_in[0];
    const float* enc_w     = (const float*)d_in[1];
    const float* enc_b     = (const float*)d_in[2];
    const float* in_proj_w = (const float*)d_in[3];
    const float* conv_w    = (const float*)d_in[4];
    const float* conv_b    = (const float*)d_in[5];
    const float* x_proj_w  = (const float*)d_in[6];
    const float* dt_w      = (const float*)d_in[7];
    const float* dt_b      = (const float*)d_in[8];
    const float* A_log     = (const float*)d_in[9];
    const float* Dv        = (const float*)d_in[10];
    const float* out_proj_w= (const float*)d_in[11];
    const float* ln_g      = (const float*)d_in[12];
    const float* ln_b      = (const float*)d_in[13];
    const float* dec_w     = (const float*)d_in[14];
    const float* dec_b     = (const float*)d_in[15];

    float *p_h, *p_xz, *p_u, *p_proj, *p_ymod, *p_out2;
    cudaGetSymbolAddress((void**)&p_h,    g_h);
    cudaGetSymbolAddress((void**)&p_xz,   g_xz);
    cudaGetSymbolAddress((void**)&p_u,    g_u);
    cudaGetSymbolAddress((void**)&p_proj, g_proj);
    cudaGetSymbolAddress((void**)&p_ymod, g_ymod);
    cudaGetSymbolAddress((void**)&p_out2, g_out2);

    enc_kernel<<<MROWS, DM>>>(x, enc_w, enc_b);

    for (int i = 0; i < NL; i++) {
        // xz = h @ in_proj_w[i]   (8192x256 @ 256x1024)
        dim3 g1((2*DI)/GBN, MROWS/GBM);
        gemm64<<<g1, 256>>>(p_h, in_proj_w + (size_t)i*DM*2*DI, p_xz, MROWS, 2*DI, DM);

        // u = silu(causal_conv(xz[:, :512]))
        conv_silu_kernel<<<MROWS, DI>>>(conv_w + (size_t)i*DI*4, conv_b + (size_t)i*DI);

        // proj = u @ x_proj_w[i]  (8192x512 @ 512x48)
        dim3 g2((PROJC + GBN - 1)/GBN, MROWS/GBM);
        gemm64<<<g2, 256>>>(p_u, x_proj_w + (size_t)i*DI*PROJC, p_proj, MROWS, PROJC, DI);

        // dt = softplus(proj[:, :16] @ dt_w[i] + dt_b[i])
        dt_kernel<<<MROWS, DI>>>(dt_w + (size_t)i*DTR*DI, dt_b + (size_t)i*DI);

        // selective scan + D skip + silu(z) gate
        scan_kernel<<<256, 256>>>(A_log + (size_t)i*DI*NST, Dv + (size_t)i*DI);

        // out2 = ymod @ out_proj_w[i]  (8192x512 @ 512x256)
        dim3 g3(DM/GBN, MROWS/GBM);
        gemm64<<<g3, 256>>>(p_ymod, out_proj_w + (size_t)i*DI*DM, p_out2, MROWS, DM, DI);

        // h = layernorm(out2 + h)
        ln_kernel<<<MROWS, DM>>>(ln_g + (size_t)i*DM, ln_b + (size_t)i*DM);
    }

    pool_kernel<<<BSZ, DM>>>();
    dec_kernel<<<1, 128>>>(dec_w, dec_b, (float*)d_out);
}

// round 2
// speedup vs baseline: 1.3751x; 1.3751x over previous
#include <cuda_runtime.h>
#include <cuda_bf16.h>
#include <math.h>

// ---------------- Problem dims (fixed by setup_inputs) ----------------
#define NL    8
#define BSZ   8
#define LSEQ  1024
#define DM    256
#define DI    512
#define NST   16
#define DTR   16
#define PROJC 48          // dt_rank + 2*N
#define MROWS (BSZ*LSEQ)  // 8192

// ---------------- Device scratch (no allocations allowed) ----------------
__device__ float g_h   [MROWS*DM];        // residual stream
__device__ float g_xz  [MROWS*2*DI];      // in_proj output
__device__ float g_u   [MROWS*DI];        // conv+silu out
__device__ float g_proj[MROWS*PROJC];     // x_proj out
__device__ float g_dt  [MROWS*DI];        // softplus(dt)
__device__ float g_ymod[MROWS*DI];        // y*silu(z)
__device__ float g_out2[MROWS*DM];        // out_proj out
__device__ float g_pooled[BSZ*DM];

// ---------------- helpers ----------------
__device__ __forceinline__ unsigned f2tf(float f) {
    unsigned r;
    asm("cvt.rna.tf32.f32 %0, %1;" : "=r"(r) : "f"(f));
    return r;
}

__device__ __forceinline__ void mma_tf32(float& d0, float& d1, float& d2, float& d3,
                                         unsigned a0, unsigned a1, unsigned a2, unsigned a3,
                                         unsigned b0, unsigned b1) {
    asm volatile(
        "mma.sync.aligned.m16n8k8.row.col.f32.tf32.tf32.f32 "
        "{%0,%1,%2,%3}, {%4,%5,%6,%7}, {%8,%9}, {%0,%1,%2,%3};\n"
        : "+f"(d0), "+f"(d1), "+f"(d2), "+f"(d3)
        : "r"(a0), "r"(a1), "r"(a2), "r"(a3), "r"(b0), "r"(b1));
}

// ---------------- Encoder: h[b,l,m] = sum_c x[b,c,l]*W[c,m] + b[m] ----------------
__global__ void enc_kernel(const float* __restrict__ x,
                           const float* __restrict__ w,
                           const float* __restrict__ bb) {
    int bl = blockIdx.x;
    int m  = threadIdx.x;
    int b = bl >> 10, l = bl & 1023;
    float acc = bb[m];
#pragma unroll
    for (int c = 0; c < 3; c++)
        acc = fmaf(x[(b*3 + c)*LSEQ + l], w[c*DM + m], acc);
    g_h[bl*DM + m] = acc;
}

// ---------------- TF32 tensor-core GEMM: C[MxN] = A[MxK] @ B[KxN] ----------------
// BM x 64 tile, BK=32. WARPS_M x 2 warp grid, warp tile 32x32 (2x4 m16n8k8 atoms).
// M multiple of BM, K multiple of 32, N guarded (for N=48).
template<int BM, int WARPS_M>
__global__ void gemm_tf32(const float* __restrict__ A,
                          const float* __restrict__ B,
                          float* __restrict__ C,
                          int M, int N, int K) {
    constexpr int NT = WARPS_M * 2 * 32;      // threads
    __shared__ unsigned As[BM * 36];          // [BM][32+4]  (4m+k)%32 unique -> conflict free
    __shared__ unsigned Bs[32 * 72];          // [32][64+8]  (8k+n)%32 unique -> conflict free

    int tid  = threadIdx.x;
    int lane = tid & 31;
    int wid  = tid >> 5;
    int wm   = wid & (WARPS_M - 1);           // warp m index
    int wn   = wid / WARPS_M;                 // warp n index (0..1)
    int m0   = blockIdx.y * BM;
    int n0   = blockIdx.x * 64;

    int r = lane >> 2;                        // 0..7
    int c = lane & 3;                         // 0..3

    float acc[2][4][4] = {};

    for (int k0 = 0; k0 < K; k0 += 32) {
        // --- A tile: BM rows x 32 k, float4 loads ---
#pragma unroll
        for (int i = tid; i < BM * 8; i += NT) {
            int row = i >> 3, c4 = i & 7;
            float4 v = *(const float4*)(A + (size_t)(m0 + row)*K + k0 + c4*4);
            unsigned* p = &As[row*36 + c4*4];
            p[0] = f2tf(v.x); p[1] = f2tf(v.y); p[2] = f2tf(v.z); p[3] = f2tf(v.w);
        }
        // --- B tile: 32 k x 64 n ---
#pragma unroll
        for (int i = tid; i < 512; i += NT) {
            int row = i >> 4, c4 = i & 15;
            int n = n0 + c4*4;
            float4 v = (n + 3 < N) ? *(const float4*)(B + (size_t)(k0 + row)*N + n)
                                   : make_float4(0.f, 0.f, 0.f, 0.f);
            unsigned* p = &Bs[row*72 + c4*4];
            p[0] = f2tf(v.x); p[1] = f2tf(v.y); p[2] = f2tf(v.z); p[3] = f2tf(v.w);
        }
        __syncthreads();

#pragma unroll
        for (int kk = 0; kk < 32; kk += 8) {
            unsigned af[2][4], bf[4][2];
#pragma unroll
            for (int am = 0; am < 2; am++) {
                int mrow = wm*32 + am*16;
                af[am][0] = As[(mrow + r    )*36 + kk + c    ];
                af[am][1] = As[(mrow + r + 8)*36 + kk + c    ];
                af[am][2] = As[(mrow + r    )*36 + kk + c + 4];
                af[am][3] = As[(mrow + r + 8)*36 + kk + c + 4];
            }
#pragma unroll
            for (int bn = 0; bn < 4; bn++) {
                int ncol = wn*32 + bn*8 + r;
                bf[bn][0] = Bs[(kk + c    )*72 + ncol];
                bf[bn][1] = Bs[(kk + c + 4)*72 + ncol];
            }
#pragma unroll
            for (int am = 0; am < 2; am++)
#pragma unroll
                for (int bn = 0; bn < 4; bn++)
                    mma_tf32(acc[am][bn][0], acc[am][bn][1], acc[am][bn][2], acc[am][bn][3],
                             af[am][0], af[am][1], af[am][2], af[am][3],
                             bf[bn][0], bf[bn][1]);
        }
        __syncthreads();
    }

    // --- epilogue ---
#pragma unroll
    for (int am = 0; am < 2; am++) {
#pragma unroll
        for (int bn = 0; bn < 4; bn++) {
            int m = m0 + wm*32 + am*16 + r;
            int n = n0 + wn*32 + bn*8 + 2*c;
            if (n + 1 < N) {
                *(float2*)(C + (size_t)m*N + n)       = make_float2(acc[am][bn][0], acc[am][bn][1]);
                *(float2*)(C + (size_t)(m + 8)*N + n) = make_float2(acc[am][bn][2], acc[am][bn][3]);
            } else if (n < N) {
                C[(size_t)m*N + n]       = acc[am][bn][0];
                C[(size_t)(m + 8)*N + n] = acc[am][bn][2];
            }
        }
    }
}

// ---------------- Causal depthwise conv (K=4) + SiLU, 4 outputs/thread ----------------
__global__ void conv_silu_kernel(const float* __restrict__ cw,
                                 const float* __restrict__ cb) {
    int d = threadIdx.x;            // 0..511
    int t = blockIdx.x;             // b*256 + lt
    int b = t >> 8, lt = t & 255;
    int l0 = lt * 4;
    float w0 = cw[d*4+0], w1 = cw[d*4+1], w2 = cw[d*4+2], w3 = cw[d*4+3];
    float bias = cb[d];
    float v[7];
#pragma unroll
    for (int j = 0; j < 7; j++) {
        int ll = l0 - 3 + j;
        v[j] = (ll >= 0) ? g_xz[(size_t)((b << 10) + ll)*(2*DI) + d] : 0.f;
    }
#pragma unroll
    for (int i = 0; i < 4; i++) {
        float acc = bias;
        acc = fmaf(v[i],   w0, acc);
        acc = fmaf(v[i+1], w1, acc);
        acc = fmaf(v[i+2], w2, acc);
        acc = fmaf(v[i+3], w3, acc);
        float s = acc / (1.f + __expf(-acc));
        g_u[(size_t)((b << 10) + l0 + i)*DI + d] = s;
    }
}

// ---------------- dt = softplus(proj[:, :16] @ dt_w + dt_b) ----------------
__global__ void dt_kernel(const float* __restrict__ dtw,
                          const float* __restrict__ dtb) {
    __shared__ float sp[DTR];
    int bl = blockIdx.x;
    int d  = threadIdx.x;           // 0..511
    if (d < DTR) sp[d] = g_proj[bl*PROJC + d];
    __syncthreads();
    float acc = dtb[d];
#pragma unroll
    for (int rr = 0; rr < DTR; rr++)
        acc = fmaf(sp[rr], dtw[rr*DI + d], acc);
    g_dt[(size_t)bl*DI + d] = (acc > 20.f) ? acc : log1pf(__expf(acc));
}

// ---------------- Selective scan + gate, SMEM-shared B/C ----------------
// Block = 256 threads = 16 halfwarp channels (same batch b, 16 consecutive d).
// B/C for (b,l) staged through SMEM in 64-step chunks (kills 512x L2 redundancy).
#define SCH 64
__global__ void scan_kernel(const float* __restrict__ A_log,
                            const float* __restrict__ Dv) {
    __shared__ float sBC[SCH][32];
    int b  = blockIdx.x >> 5;
    int d0 = (blockIdx.x & 31) * 16;
    int tid = threadIdx.x;
    int hw = tid >> 4;              // halfwarp/channel 0..15
    int n  = tid & 15;
    int d  = d0 + hw;

    float Ad = -__expf(A_log[d*NST + n]);
    float Dd = Dv[d];
    float state = 0.f;
    int blbase = b << 10;

    for (int c0 = 0; c0 < LSEQ; c0 += SCH) {
        __syncthreads();
#pragma unroll
        for (int j = 0; j < SCH*32/256; j++) {
            int idx = j*256 + tid;
            int l = idx >> 5, cc = idx & 31;
            sBC[l][cc] = g_proj[(size_t)(blbase + c0 + l)*PROJC + DTR + cc];
        }
        __syncthreads();
#pragma unroll 4
        for (int l = 0; l < SCH; l++) {
            int bl = blbase + c0 + l;
            float dtv = g_dt[(size_t)bl*DI + d];
            float uv  = g_u [(size_t)bl*DI + d];
            float Bv  = sBC[l][n];
            float Cv  = sBC[l][16 + n];
            state = fmaf(__expf(dtv*Ad), state, dtv*uv*Bv);
            float p = state * Cv;
            p += __shfl_xor_sync(0xffffffffu, p, 8);
            p += __shfl_xor_sync(0xffffffffu, p, 4);
            p += __shfl_xor_sync(0xffffffffu, p, 2);
            p += __shfl_xor_sync(0xffffffffu, p, 1);
            if (n == 0) {
                float zv = g_xz[(size_t)bl*(2*DI) + DI + d];
                float sz = zv / (1.f + __expf(-zv));
                g_ymod[(size_t)bl*DI + d] = (p + uv*Dd) * sz;
            }
        }
    }
}

// ---------------- Residual add + LayerNorm (in-place into g_h) ----------------
__global__ void ln_kernel(const float* __restrict__ gamma,
                          const float* __restrict__ beta) {
    __shared__ float s1[8], s2[8];
    int bl = blockIdx.x;
    int m  = threadIdx.x;
    float t = g_out2[bl*DM + m] + g_h[bl*DM + m];
    float v1 = t, v2 = t*t;
#pragma unroll
    for (int o = 16; o > 0; o >>= 1) {
        v1 += __shfl_xor_sync(0xffffffffu, v1, o);
        v2 += __shfl_xor_sync(0xffffffffu, v2, o);
    }
    if ((m & 31) == 0) { s1[m >> 5] = v1; s2[m >> 5] = v2; }
    __syncthreads();
    float sum = 0.f, sq = 0.f;
#pragma unroll
    for (int i = 0; i < 8; i++) { sum += s1[i]; sq += s2[i]; }
    float mean = sum * (1.f/DM);
    float var  = sq * (1.f/DM) - mean*mean;
    float rs = rsqrtf(var + 1e-5f);
    g_h[bl*DM + m] = (t - mean) * rs * gamma[m] + beta[m];
}

// ---------------- Mean pool over L ----------------
__global__ void pool_kernel() {
    int b = blockIdx.x;
    int m = threadIdx.x;
    float s = 0.f;
    for (int l = 0; l < LSEQ; l++)
        s += g_h[(size_t)((b << 10) + l)*DM + m];
    g_pooled[b*DM + m] = s * (1.f/LSEQ);
}

// ---------------- Decoder ----------------
__global__ void dec_kernel(const float* __restrict__ w,
                           const float* __restrict__ bb,
                           float* __restrict__ out) {
    int i = threadIdx.x;
    if (i < BSZ*10) {
        int b = i / 10, o = i % 10;
        float acc = bb[o];
#pragma unroll 8
        for (int m = 0; m < DM; m++)
            acc = fmaf(g_pooled[b*DM + m], w[m*10 + o], acc);
        out[i] = acc;
    }
}

// ---------------- Launch ----------------
extern "C" void kernel_launch(void* const* d_in, const int* in_sizes, int n_in,
                              void* d_out, int out_size) {
    const float* x         = (const float*)d_in[0];
    const float* enc_w     = (const float*)d_in[1];
    const float* enc_b     = (const float*)d_in[2];
    const float* in_proj_w = (const float*)d_in[3];
    const float* conv_w    = (const float*)d_in[4];
    const float* conv_b    = (const float*)d_in[5];
    const float* x_proj_w  = (const float*)d_in[6];
    const float* dt_w      = (const float*)d_in[7];
    const float* dt_b      = (const float*)d_in[8];
    const float* A_log     = (const float*)d_in[9];
    const float* Dv        = (const float*)d_in[10];
    const float* out_proj_w= (const float*)d_in[11];
    const float* ln_g      = (const float*)d_in[12];
    const float* ln_b      = (const float*)d_in[13];
    const float* dec_w     = (const float*)d_in[14];
    const float* dec_b     = (const float*)d_in[15];

    float *p_h, *p_xz, *p_u, *p_proj, *p_ymod, *p_out2;
    cudaGetSymbolAddress((void**)&p_h,    g_h);
    cudaGetSymbolAddress((void**)&p_xz,   g_xz);
    cudaGetSymbolAddress((void**)&p_u,    g_u);
    cudaGetSymbolAddress((void**)&p_proj, g_proj);
    cudaGetSymbolAddress((void**)&p_ymod, g_ymod);
    cudaGetSymbolAddress((void**)&p_out2, g_out2);

    enc_kernel<<<MROWS, DM>>>(x, enc_w, enc_b);

    for (int i = 0; i < NL; i++) {
        // xz = h @ in_proj_w[i]   (8192x256 @ 256x1024)
        gemm_tf32<128,4><<<dim3((2*DI)/64, MROWS/128), 256>>>(
            p_h, in_proj_w + (size_t)i*DM*2*DI, p_xz, MROWS, 2*DI, DM);

        // u = silu(causal_conv(xz[:, :512]))
        conv_silu_kernel<<<BSZ*256, DI>>>(conv_w + (size_t)i*DI*4, conv_b + (size_t)i*DI);

        // proj = u @ x_proj_w[i]  (8192x512 @ 512x48)
        gemm_tf32<64,2><<<dim3(1, MROWS/64), 128>>>(
            p_u, x_proj_w + (size_t)i*DI*PROJC, p_proj, MROWS, PROJC, DI);

        // dt = softplus(proj[:, :16] @ dt_w[i] + dt_b[i])
        dt_kernel<<<MROWS, DI>>>(dt_w + (size_t)i*DTR*DI, dt_b + (size_t)i*DI);

        // selective scan + D skip + silu(z) gate
        scan_kernel<<<BSZ*32, 256>>>(A_log + (size_t)i*DI*NST, Dv + (size_t)i*DI);

        // out2 = ymod @ out_proj_w[i]  (8192x512 @ 512x256)
        gemm_tf32<128,4><<<dim3(DM/64, MROWS/128), 256>>>(
            p_ymod, out_proj_w + (size_t)i*DI*DM, p_out2, MROWS, DM, DI);

        // h = layernorm(out2 + h)
        ln_kernel<<<MROWS, DM>>>(ln_g + (size_t)i*DM, ln_b + (size_t)i*DM);
    }

    pool_kernel<<<BSZ, DM>>>();
    dec_kernel<<<1, 128>>>(dec_w, dec_b, (float*)d_out);
}

// round 3
// speedup vs baseline: 1.4461x; 1.0516x over previous
#include <cuda_runtime.h>
#include <cuda_bf16.h>
#include <math.h>

// ---------------- Problem dims (fixed by setup_inputs) ----------------
#define NL    8
#define BSZ   8
#define LSEQ  1024
#define DM    256
#define DI    512
#define NST   16
#define DTR   16
#define PROJC 48          // dt_rank + 2*N
#define MROWS (BSZ*LSEQ)  // 8192

// ---------------- Device scratch (no allocations allowed) ----------------
__device__ float g_h   [MROWS*DM];
__device__ float g_xz  [MROWS*2*DI];
__device__ float g_u   [MROWS*DI];
__device__ float g_proj[MROWS*PROJC];
__device__ float g_dt  [MROWS*DI];
__device__ float g_ymod[MROWS*DI];
__device__ float g_out2[MROWS*DM];
__device__ float g_pooled[BSZ*DM];

// ---------------- helpers ----------------
__device__ __forceinline__ unsigned f2tf(float f) {
    unsigned r;
    asm("cvt.rna.tf32.f32 %0, %1;" : "=r"(r) : "f"(f));
    return r;
}

__device__ __forceinline__ void mma_tf32(float& d0, float& d1, float& d2, float& d3,
                                         unsigned a0, unsigned a1, unsigned a2, unsigned a3,
                                         unsigned b0, unsigned b1) {
    asm volatile(
        "mma.sync.aligned.m16n8k8.row.col.f32.tf32.tf32.f32 "
        "{%0,%1,%2,%3}, {%4,%5,%6,%7}, {%8,%9}, {%0,%1,%2,%3};\n"
        : "+f"(d0), "+f"(d1), "+f"(d2), "+f"(d3)
        : "r"(a0), "r"(a1), "r"(a2), "r"(a3), "r"(b0), "r"(b1));
}

// ---------------- Encoder ----------------
__global__ void enc_kernel(const float* __restrict__ x,
                           const float* __restrict__ w,
                           const float* __restrict__ bb) {
    int bl = blockIdx.x;
    int m  = threadIdx.x;
    int b = bl >> 10, l = bl & 1023;
    float acc = bb[m];
#pragma unroll
    for (int c = 0; c < 3; c++)
        acc = fmaf(x[(b*3 + c)*LSEQ + l], w[c*DM + m], acc);
    g_h[bl*DM + m] = acc;
}

// ---------------- TF32 tensor-core GEMM, double-buffered ----------------
// C[MxN] = A[MxK] @ B[KxN]. Tile 64x64x32, 128 threads (4 warps, 2x2),
// warp tile 32x32 (2x4 m16n8k8 atoms). M %64==0, K %32==0, N guarded.
__global__ void __launch_bounds__(128)
gemm_tf32_db(const float* __restrict__ A,
             const float* __restrict__ B,
             float* __restrict__ C,
             int M, int N, int K) {
    __shared__ unsigned As[2][64 * 36];   // [m][k] padded: stride 36
    __shared__ unsigned Bs[2][32 * 72];   // [k][n] padded: stride 72

    int tid  = threadIdx.x;
    int lane = tid & 31;
    int wid  = tid >> 5;
    int wm   = wid & 1;
    int wn   = wid >> 1;
    int m0   = blockIdx.y * 64;
    int n0   = blockIdx.x * 64;

    int r = lane >> 2;
    int c = lane & 3;

    // per-thread load slots: A = 4 float4 (64*8/128), B = 4 float4 (512/128)
    float4 aReg[4], bReg[4];

    auto loadA = [&](int k0) {
#pragma unroll
        for (int j = 0; j < 4; j++) {
            int i   = j*128 + tid;
            int row = i >> 3, c4 = i & 7;
            aReg[j] = *(const float4*)(A + (size_t)(m0 + row)*K + k0 + c4*4);
        }
    };
    auto loadB = [&](int k0) {
#pragma unroll
        for (int j = 0; j < 4; j++) {
            int i   = j*128 + tid;
            int row = i >> 4, c4 = i & 15;
            int n   = n0 + c4*4;
            bReg[j] = (n + 3 < N) ? *(const float4*)(B + (size_t)(k0 + row)*N + n)
                                  : make_float4(0.f, 0.f, 0.f, 0.f);
        }
    };
    auto stsA = [&](int buf) {
#pragma unroll
        for (int j = 0; j < 4; j++) {
            int i   = j*128 + tid;
            int row = i >> 3, c4 = i & 7;
            unsigned* p = &As[buf][row*36 + c4*4];
            p[0] = f2tf(aReg[j].x); p[1] = f2tf(aReg[j].y);
            p[2] = f2tf(aReg[j].z); p[3] = f2tf(aReg[j].w);
        }
    };
    auto stsB = [&](int buf) {
#pragma unroll
        for (int j = 0; j < 4; j++) {
            int i   = j*128 + tid;
            int row = i >> 4, c4 = i & 15;
            unsigned* p = &Bs[buf][row*72 + c4*4];
            p[0] = f2tf(bReg[j].x); p[1] = f2tf(bReg[j].y);
            p[2] = f2tf(bReg[j].z); p[3] = f2tf(bReg[j].w);
        }
    };

    float acc[2][4][4] = {};

    // prologue
    loadA(0); loadB(0);
    stsA(0);  stsB(0);
    __syncthreads();

    int T = K >> 5;
    for (int t = 0; t < T; t++) {
        int cur = t & 1;
        if (t + 1 < T) { loadA((t+1)*32); loadB((t+1)*32); }

#pragma unroll
        for (int kk = 0; kk < 32; kk += 8) {
            unsigned af[2][4], bf[4][2];
#pragma unroll
            for (int am = 0; am < 2; am++) {
                int mrow = wm*32 + am*16;
                af[am][0] = As[cur][(mrow + r    )*36 + kk + c    ];
                af[am][1] = As[cur][(mrow + r + 8)*36 + kk + c    ];
                af[am][2] = As[cur][(mrow + r    )*36 + kk + c + 4];
                af[am][3] = As[cur][(mrow + r + 8)*36 + kk + c + 4];
            }
#pragma unroll
            for (int bn = 0; bn < 4; bn++) {
                int ncol = wn*32 + bn*8 + r;
                bf[bn][0] = Bs[cur][(kk + c    )*72 + ncol];
                bf[bn][1] = Bs[cur][(kk + c + 4)*72 + ncol];
            }
#pragma unroll
            for (int am = 0; am < 2; am++)
#pragma unroll
                for (int bn = 0; bn < 4; bn++)
                    mma_tf32(acc[am][bn][0], acc[am][bn][1], acc[am][bn][2], acc[am][bn][3],
                             af[am][0], af[am][1], af[am][2], af[am][3],
                             bf[bn][0], bf[bn][1]);
        }

        if (t + 1 < T) {
            stsA(cur ^ 1); stsB(cur ^ 1);
            __syncthreads();
        }
    }

    // epilogue
#pragma unroll
    for (int am = 0; am < 2; am++) {
#pragma unroll
        for (int bn = 0; bn < 4; bn++) {
            int m = m0 + wm*32 + am*16 + r;
            int n = n0 + wn*32 + bn*8 + 2*c;
            if (n + 1 < N) {
                *(float2*)(C + (size_t)m*N + n)       = make_float2(acc[am][bn][0], acc[am][bn][1]);
                *(float2*)(C + (size_t)(m + 8)*N + n) = make_float2(acc[am][bn][2], acc[am][bn][3]);
            } else if (n < N) {
                C[(size_t)m*N + n]       = acc[am][bn][0];
                C[(size_t)(m + 8)*N + n] = acc[am][bn][2];
            }
        }
    }
}

// ---------------- Causal depthwise conv (K=4) + SiLU, 4 outputs/thread ----------------
__global__ void conv_silu_kernel(const float* __restrict__ cw,
                                 const float* __restrict__ cb) {
    int d = threadIdx.x;
    int t = blockIdx.x;
    int b = t >> 8, lt = t & 255;
    int l0 = lt * 4;
    float w0 = cw[d*4+0], w1 = cw[d*4+1], w2 = cw[d*4+2], w3 = cw[d*4+3];
    float bias = cb[d];
    float v[7];
#pragma unroll
    for (int j = 0; j < 7; j++) {
        int ll = l0 - 3 + j;
        v[j] = (ll >= 0) ? g_xz[(size_t)((b << 10) + ll)*(2*DI) + d] : 0.f;
    }
#pragma unroll
    for (int i = 0; i < 4; i++) {
        float acc = bias;
        acc = fmaf(v[i],   w0, acc);
        acc = fmaf(v[i+1], w1, acc);
        acc = fmaf(v[i+2], w2, acc);
        acc = fmaf(v[i+3], w3, acc);
        float s = acc / (1.f + __expf(-acc));
        g_u[(size_t)((b << 10) + l0 + i)*DI + d] = s;
    }
}

// ---------------- dt = softplus(proj[:, :16] @ dt_w + dt_b) ----------------
__global__ void dt_kernel(const float* __restrict__ dtw,
                          const float* __restrict__ dtb) {
    __shared__ float sp[DTR];
    int bl = blockIdx.x;
    int d  = threadIdx.x;
    if (d < DTR) sp[d] = g_proj[bl*PROJC + d];
    __syncthreads();
    float acc = dtb[d];
#pragma unroll
    for (int rr = 0; rr < DTR; rr++)
        acc = fmaf(sp[rr], dtw[rr*DI + d], acc);
    g_dt[(size_t)bl*DI + d] = (acc > 20.f) ? acc : log1pf(__expf(acc));
}

// ---------------- Selective scan + gate, SMEM-shared B/C ----------------
#define SCH 64
__global__ void scan_kernel(const float* __restrict__ A_log,
                            const float* __restrict__ Dv) {
    __shared__ float sBC[SCH][32];
    int b  = blockIdx.x >> 5;
    int d0 = (blockIdx.x & 31) * 16;
    int tid = threadIdx.x;
    int hw = tid >> 4;
    int n  = tid & 15;
    int d  = d0 + hw;

    float Ad = -__expf(A_log[d*NST + n]);
    float Dd = Dv[d];
    float state = 0.f;
    int blbase = b << 10;

    for (int c0 = 0; c0 < LSEQ; c0 += SCH) {
        __syncthreads();
#pragma unroll
        for (int j = 0; j < SCH*32/256; j++) {
            int idx = j*256 + tid;
            int l = idx >> 5, cc = idx & 31;
            sBC[l][cc] = g_proj[(size_t)(blbase + c0 + l)*PROJC + DTR + cc];
        }
        __syncthreads();
#pragma unroll 4
        for (int l = 0; l < SCH; l++) {
            int bl = blbase + c0 + l;
            float dtv = g_dt[(size_t)bl*DI + d];
            float uv  = g_u [(size_t)bl*DI + d];
            float Bv  = sBC[l][n];
            float Cv  = sBC[l][16 + n];
            state = fmaf(__expf(dtv*Ad), state, dtv*uv*Bv);
            float p = state * Cv;
            p += __shfl_xor_sync(0xffffffffu, p, 8);
            p += __shfl_xor_sync(0xffffffffu, p, 4);
            p += __shfl_xor_sync(0xffffffffu, p, 2);
            p += __shfl_xor_sync(0xffffffffu, p, 1);
            if (n == 0) {
                float zv = g_xz[(size_t)bl*(2*DI) + DI + d];
                float sz = zv / (1.f + __expf(-zv));
                g_ymod[(size_t)bl*DI + d] = (p + uv*Dd) * sz;
            }
        }
    }
}

// ---------------- Residual add + LayerNorm ----------------
__global__ void ln_kernel(const float* __restrict__ gamma,
                          const float* __restrict__ beta) {
    __shared__ float s1[8], s2[8];
    int bl = blockIdx.x;
    int m  = threadIdx.x;
    float t = g_out2[bl*DM + m] + g_h[bl*DM + m];
    float v1 = t, v2 = t*t;
#pragma unroll
    for (int o = 16; o > 0; o >>= 1) {
        v1 += __shfl_xor_sync(0xffffffffu, v1, o);
        v2 += __shfl_xor_sync(0xffffffffu, v2, o);
    }
    if ((m & 31) == 0) { s1[m >> 5] = v1; s2[m >> 5] = v2; }
    __syncthreads();
    float sum = 0.f, sq = 0.f;
#pragma unroll
    for (int i = 0; i < 8; i++) { sum += s1[i]; sq += s2[i]; }
    float mean = sum * (1.f/DM);
    float var  = sq * (1.f/DM) - mean*mean;
    float rs = rsqrtf(var + 1e-5f);
    g_h[bl*DM + m] = (t - mean) * rs * gamma[m] + beta[m];
}

// ---------------- Mean pool over L ----------------
__global__ void pool_kernel() {
    int b = blockIdx.x;
    int m = threadIdx.x;
    float s = 0.f;
    for (int l = 0; l < LSEQ; l++)
        s += g_h[(size_t)((b << 10) + l)*DM + m];
    g_pooled[b*DM + m] = s * (1.f/LSEQ);
}

// ---------------- Decoder ----------------
__global__ void dec_kernel(const float* __restrict__ w,
                           const float* __restrict__ bb,
                           float* __restrict__ out) {
    int i = threadIdx.x;
    if (i < BSZ*10) {
        int b = i / 10, o = i % 10;
        float acc = bb[o];
#pragma unroll 8
        for (int m = 0; m < DM; m++)
            acc = fmaf(g_pooled[b*DM + m], w[m*10 + o], acc);
        out[i] = acc;
    }
}

// ---------------- Launch ----------------
extern "C" void kernel_launch(void* const* d_in, const int* in_sizes, int n_in,
                              void* d_out, int out_size) {
    const float* x         = (const float*)d_in[0];
    const float* enc_w     = (const float*)d_in[1];
    const float* enc_b     = (const float*)d_in[2];
    const float* in_proj_w = (const float*)d_in[3];
    const float* conv_w    = (const float*)d_in[4];
    const float* conv_b    = (const float*)d_in[5];
    const float* x_proj_w  = (const float*)d_in[6];
    const float* dt_w      = (const float*)d_in[7];
    const float* dt_b      = (const float*)d_in[8];
    const float* A_log     = (const float*)d_in[9];
    const float* Dv        = (const float*)d_in[10];
    const float* out_proj_w= (const float*)d_in[11];
    const float* ln_g      = (const float*)d_in[12];
    const float* ln_b      = (const float*)d_in[13];
    const float* dec_w     = (const float*)d_in[14];
    const float* dec_b     = (const float*)d_in[15];

    float *p_h, *p_xz, *p_u, *p_proj, *p_ymod, *p_out2;
    cudaGetSymbolAddress((void**)&p_h,    g_h);
    cudaGetSymbolAddress((void**)&p_xz,   g_xz);
    cudaGetSymbolAddress((void**)&p_u,    g_u);
    cudaGetSymbolAddress((void**)&p_proj, g_proj);
    cudaGetSymbolAddress((void**)&p_ymod, g_ymod);
    cudaGetSymbolAddress((void**)&p_out2, g_out2);

    enc_kernel<<<MROWS, DM>>>(x, enc_w, enc_b);

    for (int i = 0; i < NL; i++) {
        // xz = h @ in_proj_w[i]   (8192x256 @ 256x1024)
        gemm_tf32_db<<<dim3((2*DI)/64, MROWS/64), 128>>>(
            p_h, in_proj_w + (size_t)i*DM*2*DI, p_xz, MROWS, 2*DI, DM);

        // u = silu(causal_conv(xz[:, :512]))
        conv_silu_kernel<<<BSZ*256, DI>>>(conv_w + (size_t)i*DI*4, conv_b + (size_t)i*DI);

        // proj = u @ x_proj_w[i]  (8192x512 @ 512x48)
        gemm_tf32_db<<<dim3(1, MROWS/64), 128>>>(
            p_u, x_proj_w + (size_t)i*DI*PROJC, p_proj, MROWS, PROJC, DI);

        // dt = softplus(proj[:, :16] @ dt_w[i] + dt_b[i])
        dt_kernel<<<MROWS, DI>>>(dt_w + (size_t)i*DTR*DI, dt_b + (size_t)i*DI);

        // selective scan + D skip + silu(z) gate
        scan_kernel<<<BSZ*32, 256>>>(A_log + (size_t)i*DI*NST, Dv + (size_t)i*DI);

        // out2 = ymod @ out_proj_w[i]  (8192x512 @ 512x256)
        gemm_tf32_db<<<dim3(DM/64, MROWS/64), 128>>>(
            p_ymod, out_proj_w + (size_t)i*DI*DM, p_out2, MROWS, DM, DI);

        // h = layernorm(out2 + h)
        ln_kernel<<<MROWS, DM>>>(ln_g + (size_t)i*DM, ln_b + (size_t)i*DM);
    }

    pool_kernel<<<BSZ, DM>>>();
    dec_kernel<<<1, 128>>>(dec_w, dec_b, (float*)d_out);
}

// round 4
// speedup vs baseline: 1.6997x; 1.1754x over previous
#include <cuda_runtime.h>
#include <cuda_bf16.h>
#include <math.h>

// ---------------- Problem dims ----------------
#define NL    8
#define BSZ   8
#define LSEQ  1024
#define DM    256
#define DI    512
#define NST   16
#define DTR   16
#define PROJC 48
#define MROWS (BSZ*LSEQ)  // 8192

// ---------------- Device scratch ----------------
__device__ float g_h   [MROWS*DM];
__device__ float g_xz  [MROWS*2*DI];
__device__ float g_u   [MROWS*DI];
__device__ float g_proj[MROWS*PROJC];
__device__ float g_ymod[MROWS*DI];
__device__ float g_out2[MROWS*DM];
__device__ float g_pooled[BSZ*DM];

// ---------------- helpers ----------------
__device__ __forceinline__ void mma_tf32(float& d0, float& d1, float& d2, float& d3,
                                         unsigned a0, unsigned a1, unsigned a2, unsigned a3,
                                         unsigned b0, unsigned b1) {
    asm volatile(
        "mma.sync.aligned.m16n8k8.row.col.f32.tf32.tf32.f32 "
        "{%0,%1,%2,%3}, {%4,%5,%6,%7}, {%8,%9}, {%0,%1,%2,%3};\n"
        : "+f"(d0), "+f"(d1), "+f"(d2), "+f"(d3)
        : "r"(a0), "r"(a1), "r"(a2), "r"(a3), "r"(b0), "r"(b1));
}

__device__ __forceinline__ void cp16(unsigned dst, const void* src) {
    asm volatile("cp.async.cg.shared.global [%0], [%1], 16;\n" :: "r"(dst), "l"(src));
}
__device__ __forceinline__ void cp_commit() {
    asm volatile("cp.async.commit_group;\n");
}
__device__ __forceinline__ void cp_wait1() {
    asm volatile("cp.async.wait_group 1;\n");
}

// ---------------- Encoder ----------------
__global__ void enc_kernel(const float* __restrict__ x,
                           const float* __restrict__ w,
                           const float* __restrict__ bb) {
    int bl = blockIdx.x;
    int m  = threadIdx.x;
    int b = bl >> 10, l = bl & 1023;
    float acc = bb[m];
#pragma unroll
    for (int c = 0; c < 3; c++)
        acc = fmaf(x[(b*3 + c)*LSEQ + l], w[c*DM + m], acc);
    g_h[bl*DM + m] = acc;
}

// ---------------- TF32 GEMM, cp.async 3-stage pipeline ----------------
// C[MxN] = A[MxK] @ B[KxN]. Tile 128x64x16, 256 threads (8 warps: 4m x 2n),
// warp tile 32x32. M%128==0, K%16==0, N guarded. fp32 bits fed as tf32 (RZ).
#define ASTR 20   // 16 + 4 pad: banks (4r+c) conflict-free
#define BSTR 72   // 64 + 8 pad: banks (8c+n) conflict-free
__global__ void __launch_bounds__(256)
gemm_tf32_cp(const float* __restrict__ A,
             const float* __restrict__ B,
             float* __restrict__ C,
             int M, int N, int K) {
    __shared__ unsigned As[3][128*ASTR];   // [m][k]
    __shared__ unsigned Bs[3][32*BSTR];    // [k][n] (only first 16 k-rows used)

    const int tid  = threadIdx.x;
    const int lane = tid & 31;
    const int wid  = tid >> 5;
    const int wm   = wid & 3;
    const int wn   = wid >> 2;
    const int m0   = blockIdx.y * 128;
    const int n0   = blockIdx.x * 64;
    const int r = lane >> 2;
    const int c = lane & 3;

    // zero-fill B pad columns when the N tile is partial (x_proj, N=48)
    if (n0 + 64 > N) {
#pragma unroll
        for (int s = 0; s < 3; s++)
            for (int i = tid; i < 16*BSTR; i += 256)
                Bs[s][i] = 0u;
    }

    // per-thread cp.async slots
    const int aRow = (tid*2) >> 2;         // A: 2 slots (512 slots of 16B)
    const int aKq0 = (tid*2) & 3;
    const int bRow = tid >> 4;             // B: 1 slot (256 slots of 16B)
    const int bNq  = tid & 15;
    const bool bOk = (n0 + bNq*4 + 3) < N;

    unsigned aBase[3], bBase[3];
#pragma unroll
    for (int s = 0; s < 3; s++) {
        aBase[s] = (unsigned)__cvta_generic_to_shared(&As[s][0]);
        bBase[s] = (unsigned)__cvta_generic_to_shared(&Bs[s][0]);
    }

    auto loadTile = [&](int t, int s) {
        int k0 = t * 16;
        cp16(aBase[s] + (aRow*ASTR + aKq0*4)*4,
             A + (size_t)(m0 + aRow)*K + k0 + aKq0*4);
        cp16(aBase[s] + ((aRow)*ASTR + (aKq0+1)*4)*4,
             A + (size_t)(m0 + aRow)*K + k0 + (aKq0+1)*4);
        if (bOk)
            cp16(bBase[s] + (bRow*BSTR + bNq*4)*4,
                 B + (size_t)(k0 + bRow)*N + n0 + bNq*4);
        cp_commit();
    };

    float acc[2][4][4] = {};
    const int T = K >> 4;

    loadTile(0, 0);
    loadTile(1, 1);

    for (int t = 0; t < T; t++) {
        int cur = t % 3;
        cp_wait1();
        __syncthreads();
        if (t + 2 < T) loadTile(t + 2, (t + 2) % 3);

        const unsigned* Ab = As[cur];
        const unsigned* Bb = Bs[cur];
#pragma unroll
        for (int kk = 0; kk < 16; kk += 8) {
            unsigned af[2][4], bf[4][2];
#pragma unroll
            for (int am = 0; am < 2; am++) {
                int mrow = wm*32 + am*16;
                af[am][0] = Ab[(mrow + r    )*ASTR + kk + c    ];
                af[am][1] = Ab[(mrow + r + 8)*ASTR + kk + c    ];
                af[am][2] = Ab[(mrow + r    )*ASTR + kk + c + 4];
                af[am][3] = Ab[(mrow + r + 8)*ASTR + kk + c + 4];
            }
#pragma unroll
            for (int bn = 0; bn < 4; bn++) {
                int ncol = wn*32 + bn*8 + r;
                bf[bn][0] = Bb[(kk + c    )*BSTR + ncol];
                bf[bn][1] = Bb[(kk + c + 4)*BSTR + ncol];
            }
#pragma unroll
            for (int am = 0; am < 2; am++)
#pragma unroll
                for (int bn = 0; bn < 4; bn++)
                    mma_tf32(acc[am][bn][0], acc[am][bn][1], acc[am][bn][2], acc[am][bn][3],
                             af[am][0], af[am][1], af[am][2], af[am][3],
                             bf[bn][0], bf[bn][1]);
        }
        __syncthreads();
    }

    // epilogue
#pragma unroll
    for (int am = 0; am < 2; am++) {
#pragma unroll
        for (int bn = 0; bn < 4; bn++) {
            int m = m0 + wm*32 + am*16 + r;
            int n = n0 + wn*32 + bn*8 + 2*c;
            if (n + 1 < N) {
                *(float2*)(C + (size_t)m*N + n)       = make_float2(acc[am][bn][0], acc[am][bn][1]);
                *(float2*)(C + (size_t)(m + 8)*N + n) = make_float2(acc[am][bn][2], acc[am][bn][3]);
            } else if (n < N) {
                C[(size_t)m*N + n]       = acc[am][bn][0];
                C[(size_t)(m + 8)*N + n] = acc[am][bn][2];
            }
        }
    }
}

// ---------------- Causal depthwise conv (K=4) + SiLU ----------------
__global__ void conv_silu_kernel(const float* __restrict__ cw,
                                 const float* __restrict__ cb) {
    int d = threadIdx.x;
    int t = blockIdx.x;
    int b = t >> 8, lt = t & 255;
    int l0 = lt * 4;
    float w0 = cw[d*4+0], w1 = cw[d*4+1], w2 = cw[d*4+2], w3 = cw[d*4+3];
    float bias = cb[d];
    float v[7];
#pragma unroll
    for (int j = 0; j < 7; j++) {
        int ll = l0 - 3 + j;
        v[j] = (ll >= 0) ? g_xz[(size_t)((b << 10) + ll)*(2*DI) + d] : 0.f;
    }
#pragma unroll
    for (int i = 0; i < 4; i++) {
        float acc = bias;
        acc = fmaf(v[i],   w0, acc);
        acc = fmaf(v[i+1], w1, acc);
        acc = fmaf(v[i+2], w2, acc);
        acc = fmaf(v[i+3], w3, acc);
        float s = acc / (1.f + __expf(-acc));
        g_u[(size_t)((b << 10) + l0 + i)*DI + d] = s;
    }
}

// ---------------- Fused dt + selective scan + gate ----------------
// Block = 256 threads = 16 halfwarp channels (batch b, 16 consecutive d).
// proj rows staged in SMEM; dt computed in-kernel (softplus(proj[:, :16]@dtw+dtb)),
// one future step per lane, broadcast by shfl.
__global__ void __launch_bounds__(256)
scan_kernel(const float* __restrict__ A_log,
            const float* __restrict__ Dv,
            const float* __restrict__ dtw,
            const float* __restrict__ dtb) {
    __shared__ float sp[64*49];          // 64 proj rows, stride 49 (conflict-free)
    int b  = blockIdx.x >> 5;
    int d0 = (blockIdx.x & 31) * 16;
    int tid = threadIdx.x;
    int hw = tid >> 4;
    int n  = tid & 15;
    int d  = d0 + hw;
    int hbase = (tid & 31) & 16;         // 0 or 16: halfwarp base within warp

    float wdt[DTR];
#pragma unroll
    for (int r = 0; r < DTR; r++) wdt[r] = dtw[r*DI + d];
    float dtbv = dtb[d];
    float Ad = -__expf(A_log[d*NST + n]);
    float Dd = Dv[d];
    float state = 0.f;
    int blbase = b << 10;

    for (int c0 = 0; c0 < LSEQ; c0 += 64) {
        __syncthreads();
        for (int idx = tid; idx < 64*PROJC; idx += 256) {
            int l = idx / PROJC, rr = idx - l*PROJC;
            sp[l*49 + rr] = g_proj[(size_t)(blbase + c0 + l)*PROJC + rr];
        }
        __syncthreads();

        // dt for step l = j*16 + n  (this lane's share)
        float dtv4[4];
#pragma unroll
        for (int j = 0; j < 4; j++) {
            float a = dtbv;
            const float* row = &sp[(j*16 + n)*49];
#pragma unroll
            for (int r = 0; r < DTR; r++) a = fmaf(row[r], wdt[r], a);
            dtv4[j] = (a > 20.f) ? a : log1pf(__expf(a));
        }

#pragma unroll 4
        for (int l = 0; l < 64; l++) {
            float dtv = __shfl_sync(0xffffffffu, dtv4[l >> 4], hbase + (l & 15), 32);
            int bl = blbase + c0 + l;
            float uv = g_u[(size_t)bl*DI + d];
            float Bv = sp[l*49 + DTR + n];
            float Cv = sp[l*49 + DTR + NST + n];
            state = fmaf(__expf(dtv*Ad), state, dtv*uv*Bv);
            float p = state * Cv;
            p += __shfl_xor_sync(0xffffffffu, p, 8);
            p += __shfl_xor_sync(0xffffffffu, p, 4);
            p += __shfl_xor_sync(0xffffffffu, p, 2);
            p += __shfl_xor_sync(0xffffffffu, p, 1);
            if (n == 0) {
                float zv = g_xz[(size_t)bl*(2*DI) + DI + d];
                float sz = zv / (1.f + __expf(-zv));
                g_ymod[(size_t)bl*DI + d] = (p + uv*Dd) * sz;
            }
        }
    }
}

// ---------------- Residual add + LayerNorm ----------------
__global__ void ln_kernel(const float* __restrict__ gamma,
                          const float* __restrict__ beta) {
    __shared__ float s1[8], s2[8];
    int bl = blockIdx.x;
    int m  = threadIdx.x;
    float t = g_out2[bl*DM + m] + g_h[bl*DM + m];
    float v1 = t, v2 = t*t;
#pragma unroll
    for (int o = 16; o > 0; o >>= 1) {
        v1 += __shfl_xor_sync(0xffffffffu, v1, o);
        v2 += __shfl_xor_sync(0xffffffffu, v2, o);
    }
    if ((m & 31) == 0) { s1[m >> 5] = v1; s2[m >> 5] = v2; }
    __syncthreads();
    float sum = 0.f, sq = 0.f;
#pragma unroll
    for (int i = 0; i < 8; i++) { sum += s1[i]; sq += s2[i]; }
    float mean = sum * (1.f/DM);
    float var  = sq * (1.f/DM) - mean*mean;
    float rs = rsqrtf(var + 1e-5f);
    g_h[bl*DM + m] = (t - mean) * rs * gamma[m] + beta[m];
}

// ---------------- Mean pool ----------------
__global__ void pool_kernel() {
    int b = blockIdx.x;
    int m = threadIdx.x;
    float s = 0.f;
    for (int l = 0; l < LSEQ; l++)
        s += g_h[(size_t)((b << 10) + l)*DM + m];
    g_pooled[b*DM + m] = s * (1.f/LSEQ);
}

// ---------------- Decoder ----------------
__global__ void dec_kernel(const float* __restrict__ w,
                           const float* __restrict__ bb,
                           float* __restrict__ out) {
    int i = threadIdx.x;
    if (i < BSZ*10) {
        int b = i / 10, o = i % 10;
        float acc = bb[o];
#pragma unroll 8
        for (int m = 0; m < DM; m++)
            acc = fmaf(g_pooled[b*DM + m], w[m*10 + o], acc);
        out[i] = acc;
    }
}

// ---------------- Launch ----------------
extern "C" void kernel_launch(void* const* d_in, const int* in_sizes, int n_in,
                              void* d_out, int out_size) {
    const float* x         = (const float*)d_in[0];
    const float* enc_w     = (const float*)d_in[1];
    const float* enc_b     = (const float*)d_in[2];
    const float* in_proj_w = (const float*)d_in[3];
    const float* conv_w    = (const float*)d_in[4];
    const float* conv_b    = (const float*)d_in[5];
    const float* x_proj_w  = (const float*)d_in[6];
    const float* dt_w      = (const float*)d_in[7];
    const float* dt_b      = (const float*)d_in[8];
    const float* A_log     = (const float*)d_in[9];
    const float* Dv        = (const float*)d_in[10];
    const float* out_proj_w= (const float*)d_in[11];
    const float* ln_g      = (const float*)d_in[12];
    const float* ln_b      = (const float*)d_in[13];
    const float* dec_w     = (const float*)d_in[14];
    const float* dec_b     = (const float*)d_in[15];

    float *p_h, *p_xz, *p_u, *p_proj, *p_ymod, *p_out2;
    cudaGetSymbolAddress((void**)&p_h,    g_h);
    cudaGetSymbolAddress((void**)&p_xz,   g_xz);
    cudaGetSymbolAddress((void**)&p_u,    g_u);
    cudaGetSymbolAddress((void**)&p_proj, g_proj);
    cudaGetSymbolAddress((void**)&p_ymod, g_ymod);
    cudaGetSymbolAddress((void**)&p_out2, g_out2);

    enc_kernel<<<MROWS, DM>>>(x, enc_w, enc_b);

    for (int i = 0; i < NL; i++) {
        // xz = h @ in_proj_w[i]   (8192x256 @ 256x1024)
        gemm_tf32_cp<<<dim3((2*DI)/64, MROWS/128), 256>>>(
            p_h, in_proj_w + (size_t)i*DM*2*DI, p_xz, MROWS, 2*DI, DM);

        // u = silu(causal_conv(xz[:, :512]))
        conv_silu_kernel<<<BSZ*256, DI>>>(conv_w + (size_t)i*DI*4, conv_b + (size_t)i*DI);

        // proj = u @ x_proj_w[i]  (8192x512 @ 512x48)
        gemm_tf32_cp<<<dim3(1, MROWS/128), 256>>>(
            p_u, x_proj_w + (size_t)i*DI*PROJC, p_proj, MROWS, PROJC, DI);

        // fused dt + selective scan + D skip + silu(z) gate
        scan_kernel<<<BSZ*32, 256>>>(A_log + (size_t)i*DI*NST, Dv + (size_t)i*DI,
                                     dt_w + (size_t)i*DTR*DI, dt_b + (size_t)i*DI);

        // out2 = ymod @ out_proj_w[i]  (8192x512 @ 512x256)
        gemm_tf32_cp<<<dim3(DM/64, MROWS/128), 256>>>(
            p_ymod, out_proj_w + (size_t)i*DI*DM, p_out2, MROWS, DM, DI);

        // h = layernorm(out2 + h)
        ln_kernel<<<MROWS, DM>>>(ln_g + (size_t)i*DM, ln_b + (size_t)i*DM);
    }

    pool_kernel<<<BSZ, DM>>>();
    dec_kernel<<<1, 128>>>(dec_w, dec_b, (float*)d_out);
}

// round 5
// speedup vs baseline: 3.5738x; 2.1025x over previous
#include <cuda_runtime.h>
#include <cuda_bf16.h>
#include <math.h>

// ---------------- Problem dims ----------------
#define NL    8
#define BSZ   8
#define LSEQ  1024
#define DM    256
#define DI    512
#define NST   16
#define DTR   16
#define PROJC 48
#define MROWS (BSZ*LSEQ)  // 8192

// ---------------- Device scratch ----------------
__device__ float g_h   [MROWS*DM];
__device__ float g_xz  [MROWS*2*DI];
__device__ float g_u   [MROWS*DI];
__device__ float g_proj[MROWS*PROJC];
__device__ float g_ymod[MROWS*DI];
__device__ float g_out2[MROWS*DM];
__device__ float g_pooled[BSZ*DM];

// ---------------- helpers ----------------
__device__ __forceinline__ void mma_tf32(float& d0, float& d1, float& d2, float& d3,
                                         unsigned a0, unsigned a1, unsigned a2, unsigned a3,
                                         unsigned b0, unsigned b1) {
    asm volatile(
        "mma.sync.aligned.m16n8k8.row.col.f32.tf32.tf32.f32 "
        "{%0,%1,%2,%3}, {%4,%5,%6,%7}, {%8,%9}, {%0,%1,%2,%3};\n"
        : "+f"(d0), "+f"(d1), "+f"(d2), "+f"(d3)
        : "r"(a0), "r"(a1), "r"(a2), "r"(a3), "r"(b0), "r"(b1));
}
__device__ __forceinline__ void cp16(unsigned dst, const void* src) {
    asm volatile("cp.async.cg.shared.global [%0], [%1], 16;\n" :: "r"(dst), "l"(src));
}
__device__ __forceinline__ void cp_commit() { asm volatile("cp.async.commit_group;\n"); }
__device__ __forceinline__ void cp_wait0()  { asm volatile("cp.async.wait_group 0;\n"); }
__device__ __forceinline__ void cp_wait1()  { asm volatile("cp.async.wait_group 1;\n"); }

// ---------------- Encoder ----------------
__global__ void enc_kernel(const float* __restrict__ x,
                           const float* __restrict__ w,
                           const float* __restrict__ bb) {
    int bl = blockIdx.x;
    int m  = threadIdx.x;
    int b = bl >> 10, l = bl & 1023;
    float acc = bb[m];
#pragma unroll
    for (int c = 0; c < 3; c++)
        acc = fmaf(x[(b*3 + c)*LSEQ + l], w[c*DM + m], acc);
    g_h[bl*DM + m] = acc;
}

// ---------------- TF32 GEMM, cp.async 3-stage pipeline ----------------
// Tile 128x64x16, 256 threads (8 warps: 4m x 2n), warp tile 32x32.
// M%128==0, K%16==0, N guarded. fp32 bits fed as tf32 (RZ).
#define ASTR 20
#define BSTR 72
__global__ void __launch_bounds__(256, 2)
gemm_tf32_cp(const float* __restrict__ A,
             const float* __restrict__ B,
             float* __restrict__ C,
             int M, int N, int K) {
    __shared__ unsigned As[3][128*ASTR];   // 30.7 KB
    __shared__ unsigned Bs[3][16*BSTR];    // 13.8 KB

    const int tid  = threadIdx.x;
    const int lane = tid & 31;
    const int wid  = tid >> 5;
    const int wm   = wid & 3;
    const int wn   = wid >> 2;
    const int m0   = blockIdx.y * 128;
    const int n0   = blockIdx.x * 64;
    const int r = lane >> 2;
    const int c = lane & 3;

    if (n0 + 64 > N) {
#pragma unroll
        for (int s = 0; s < 3; s++)
            for (int i = tid; i < 16*BSTR; i += 256)
                Bs[s][i] = 0u;
        __syncthreads();
    }

    const int aRow = tid >> 1;
    const int aKq0 = (tid & 1) * 2;
    const int bRow = tid >> 4;
    const int bNq  = tid & 15;
    const bool bOk = (n0 + bNq*4 + 3) < N;

    unsigned aBase[3], bBase[3];
#pragma unroll
    for (int s = 0; s < 3; s++) {
        aBase[s] = (unsigned)__cvta_generic_to_shared(&As[s][0]);
        bBase[s] = (unsigned)__cvta_generic_to_shared(&Bs[s][0]);
    }

    auto loadTile = [&](int t, int s) {
        int k0 = t * 16;
        cp16(aBase[s] + (aRow*ASTR + aKq0*4)*4,
             A + (size_t)(m0 + aRow)*K + k0 + aKq0*4);
        cp16(aBase[s] + (aRow*ASTR + (aKq0+1)*4)*4,
             A + (size_t)(m0 + aRow)*K + k0 + (aKq0+1)*4);
        if (bOk)
            cp16(bBase[s] + (bRow*BSTR + bNq*4)*4,
                 B + (size_t)(k0 + bRow)*N + n0 + bNq*4);
        cp_commit();
    };

    float acc[2][4][4] = {};
    const int T = K >> 4;

    loadTile(0, 0);
    loadTile(1, 1);

    for (int t = 0; t < T; t++) {
        int cur = t % 3;
        cp_wait1();
        __syncthreads();
        if (t + 2 < T) loadTile(t + 2, (t + 2) % 3);

        const unsigned* Ab = As[cur];
        const unsigned* Bb = Bs[cur];
#pragma unroll
        for (int kk = 0; kk < 16; kk += 8) {
            unsigned af[2][4], bf[4][2];
#pragma unroll
            for (int am = 0; am < 2; am++) {
                int mrow = wm*32 + am*16;
                af[am][0] = Ab[(mrow + r    )*ASTR + kk + c    ];
                af[am][1] = Ab[(mrow + r + 8)*ASTR + kk + c    ];
                af[am][2] = Ab[(mrow + r    )*ASTR + kk + c + 4];
                af[am][3] = Ab[(mrow + r + 8)*ASTR + kk + c + 4];
            }
#pragma unroll
            for (int bn = 0; bn < 4; bn++) {
                int ncol = wn*32 + bn*8 + r;
                bf[bn][0] = Bb[(kk + c    )*BSTR + ncol];
                bf[bn][1] = Bb[(kk + c + 4)*BSTR + ncol];
            }
#pragma unroll
            for (int am = 0; am < 2; am++)
#pragma unroll
                for (int bn = 0; bn < 4; bn++)
                    mma_tf32(acc[am][bn][0], acc[am][bn][1], acc[am][bn][2], acc[am][bn][3],
                             af[am][0], af[am][1], af[am][2], af[am][3],
                             bf[bn][0], bf[bn][1]);
        }
        __syncthreads();
    }

#pragma unroll
    for (int am = 0; am < 2; am++) {
#pragma unroll
        for (int bn = 0; bn < 4; bn++) {
            int m = m0 + wm*32 + am*16 + r;
            int n = n0 + wn*32 + bn*8 + 2*c;
            if (n + 1 < N) {
                *(float2*)(C + (size_t)m*N + n)       = make_float2(acc[am][bn][0], acc[am][bn][1]);
                *(float2*)(C + (size_t)(m + 8)*N + n) = make_float2(acc[am][bn][2], acc[am][bn][3]);
            } else if (n < N) {
                C[(size_t)m*N + n]       = acc[am][bn][0];
                C[(size_t)(m + 8)*N + n] = acc[am][bn][2];
            }
        }
    }
}

// ---------------- Causal depthwise conv (K=4) + SiLU ----------------
__global__ void conv_silu_kernel(const float* __restrict__ cw,
                                 const float* __restrict__ cb) {
    int d = threadIdx.x;
    int t = blockIdx.x;
    int b = t >> 8, lt = t & 255;
    int l0 = lt * 4;
    float w0 = cw[d*4+0], w1 = cw[d*4+1], w2 = cw[d*4+2], w3 = cw[d*4+3];
    float bias = cb[d];
    float v[7];
#pragma unroll
    for (int j = 0; j < 7; j++) {
        int ll = l0 - 3 + j;
        v[j] = (ll >= 0) ? g_xz[(size_t)((b << 10) + ll)*(2*DI) + d] : 0.f;
    }
#pragma unroll
    for (int i = 0; i < 4; i++) {
        float acc = bias;
        acc = fmaf(v[i],   w0, acc);
        acc = fmaf(v[i+1], w1, acc);
        acc = fmaf(v[i+2], w2, acc);
        acc = fmaf(v[i+3], w3, acc);
        float s = acc / (1.f + __expf(-acc));
        g_u[(size_t)((b << 10) + l0 + i)*DI + d] = s;
    }
}

// ---------------- Fused dt + selective scan + gate, cp.async staged ----------------
// Block = 256 threads = 16 halfwarp channels (batch b, 16 consecutive d).
// Per 64-step chunk: proj/u/z prefetched via cp.async (double buffered),
// dt computed in-kernel, output staged in SMEM -> coalesced float4 stores.
#define SCH 64
#define SPSTR 52   // 48 + 4 pad, 16B-aligned stride
__global__ void __launch_bounds__(256)
scan_kernel(const float* __restrict__ A_log,
            const float* __restrict__ Dv,
            const float* __restrict__ dtw,
            const float* __restrict__ dtb) {
    __shared__ float sp[2][SCH*SPSTR];   // proj rows      (26.6 KB)
    __shared__ float su[2][SCH*16];      // u              (8 KB)
    __shared__ float sz[2][SCH*16];      // z              (8 KB)
    __shared__ float so[SCH*16];         // output staging (4 KB)

    const int b  = blockIdx.x >> 5;
    const int d0 = (blockIdx.x & 31) * 16;
    const int tid = threadIdx.x;
    const int hw = tid >> 4;
    const int n  = tid & 15;
    const int d  = d0 + hw;
    const int hbase = (tid & 31) & 16;
    const int blbase = b << 10;

    // cp.async slot mapping
    const int rl = tid >> 2;        // u/z/out row 0..63
    const int rq = tid & 3;         // quad within 16 floats

    unsigned spB[2], suB[2], szB[2];
#pragma unroll
    for (int s = 0; s < 2; s++) {
        spB[s] = (unsigned)__cvta_generic_to_shared(&sp[s][0]);
        suB[s] = (unsigned)__cvta_generic_to_shared(&su[s][0]);
        szB[s] = (unsigned)__cvta_generic_to_shared(&sz[s][0]);
    }

    auto loadChunk = [&](int c0, int buf) {
        cp16(suB[buf] + (rl*16 + rq*4)*4,
             g_u + (size_t)(blbase + c0 + rl)*DI + d0 + rq*4);
        cp16(szB[buf] + (rl*16 + rq*4)*4,
             g_xz + (size_t)(blbase + c0 + rl)*(2*DI) + DI + d0 + rq*4);
#pragma unroll
        for (int k = 0; k < 3; k++) {
            int s = tid + k*256;
            int l = s / 12, q = s - l*12;
            cp16(spB[buf] + (l*SPSTR + q*4)*4,
                 g_proj + (size_t)(blbase + c0 + l)*PROJC + q*4);
        }
        cp_commit();
    };

    float wdt[DTR];
#pragma unroll
    for (int r = 0; r < DTR; r++) wdt[r] = dtw[r*DI + d];
    const float dtbv = dtb[d];
    const float Ad = -__expf(A_log[d*NST + n]);
    const float Dd = Dv[d];
    float state = 0.f;

    loadChunk(0, 0);

    for (int cc = 0; cc < LSEQ/SCH; cc++) {
        int buf = cc & 1;
        if (cc + 1 < LSEQ/SCH) { loadChunk((cc+1)*SCH, buf ^ 1); cp_wait1(); }
        else                   { cp_wait0(); }
        __syncthreads();

        const float* P = sp[buf];
        const float* U = su[buf];
        const float* Z = sz[buf];

        // dt for step l = j*16 + n (this lane's share)
        float dtv4[4];
#pragma unroll
        for (int j = 0; j < 4; j++) {
            float a = dtbv;
            const float* row = &P[(j*16 + n)*SPSTR];
#pragma unroll
            for (int r = 0; r < DTR; r++) a = fmaf(row[r], wdt[r], a);
            dtv4[j] = (a > 20.f) ? a : log1pf(__expf(a));
        }

#pragma unroll 4
        for (int l = 0; l < SCH; l++) {
            float dtv = __shfl_sync(0xffffffffu, dtv4[l >> 4], hbase + (l & 15), 32);
            float uv = U[l*16 + hw];
            float Bv = P[l*SPSTR + DTR + n];
            float Cv = P[l*SPSTR + DTR + NST + n];
            state = fmaf(__expf(dtv*Ad), state, dtv*uv*Bv);
            float p = state * Cv;
            p += __shfl_xor_sync(0xffffffffu, p, 8);
            p += __shfl_xor_sync(0xffffffffu, p, 4);
            p += __shfl_xor_sync(0xffffffffu, p, 2);
            p += __shfl_xor_sync(0xffffffffu, p, 1);
            if (n == 0) {
                float zv = Z[l*16 + hw];
                float sz_ = zv / (1.f + __expf(-zv));
                so[l*16 + hw] = (p + uv*Dd) * sz_;
            }
        }
        __syncthreads();

        // coalesced writeback
        {
            float4 v = *(const float4*)&so[rl*16 + rq*4];
            *(float4*)(g_ymod + (size_t)(blbase + cc*SCH + rl)*DI + d0 + rq*4) = v;
        }
    }
}

// ---------------- Residual add + LayerNorm ----------------
__global__ void ln_kernel(const float* __restrict__ gamma,
                          const float* __restrict__ beta) {
    __shared__ float s1[8], s2[8];
    int bl = blockIdx.x;
    int m  = threadIdx.x;
    float t = g_out2[bl*DM + m] + g_h[bl*DM + m];
    float v1 = t, v2 = t*t;
#pragma unroll
    for (int o = 16; o > 0; o >>= 1) {
        v1 += __shfl_xor_sync(0xffffffffu, v1, o);
        v2 += __shfl_xor_sync(0xffffffffu, v2, o);
    }
    if ((m & 31) == 0) { s1[m >> 5] = v1; s2[m >> 5] = v2; }
    __syncthreads();
    float sum = 0.f, sq = 0.f;
#pragma unroll
    for (int i = 0; i < 8; i++) { sum += s1[i]; sq += s2[i]; }
    float mean = sum * (1.f/DM);
    float var  = sq * (1.f/DM) - mean*mean;
    float rs = rsqrtf(var + 1e-5f);
    g_h[bl*DM + m] = (t - mean) * rs * gamma[m] + beta[m];
}

// ---------------- Mean pool ----------------
__global__ void pool_kernel() {
    int b = blockIdx.x;
    int m = threadIdx.x;
    float s = 0.f;
    for (int l = 0; l < LSEQ; l++)
        s += g_h[(size_t)((b << 10) + l)*DM + m];
    g_pooled[b*DM + m] = s * (1.f/LSEQ);
}

// ---------------- Decoder ----------------
__global__ void dec_kernel(const float* __restrict__ w,
                           const float* __restrict__ bb,
                           float* __restrict__ out) {
    int i = threadIdx.x;
    if (i < BSZ*10) {
        int b = i / 10, o = i % 10;
        float acc = bb[o];
#pragma unroll 8
        for (int m = 0; m < DM; m++)
            acc = fmaf(g_pooled[b*DM + m], w[m*10 + o], acc);
        out[i] = acc;
    }
}

// ---------------- Launch ----------------
extern "C" void kernel_launch(void* const* d_in, const int* in_sizes, int n_in,
                              void* d_out, int out_size) {
    const float* x         = (const float*)d_in[0];
    const float* enc_w     = (const float*)d_in[1];
    const float* enc_b     = (const float*)d_in[2];
    const float* in_proj_w = (const float*)d_in[3];
    const float* conv_w    = (const float*)d_in[4];
    const float* conv_b    = (const float*)d_in[5];
    const float* x_proj_w  = (const float*)d_in[6];
    const float* dt_w      = (const float*)d_in[7];
    const float* dt_b      = (const float*)d_in[8];
    const float* A_log     = (const float*)d_in[9];
    const float* Dv        = (const float*)d_in[10];
    const float* out_proj_w= (const float*)d_in[11];
    const float* ln_g      = (const float*)d_in[12];
    const float* ln_b      = (const float*)d_in[13];
    const float* dec_w     = (const float*)d_in[14];
    const float* dec_b     = (const float*)d_in[15];

    float *p_h, *p_xz, *p_u, *p_proj, *p_ymod, *p_out2;
    cudaGetSymbolAddress((void**)&p_h,    g_h);
    cudaGetSymbolAddress((void**)&p_xz,   g_xz);
    cudaGetSymbolAddress((void**)&p_u,    g_u);
    cudaGetSymbolAddress((void**)&p_proj, g_proj);
    cudaGetSymbolAddress((void**)&p_ymod, g_ymod);
    cudaGetSymbolAddress((void**)&p_out2, g_out2);

    enc_kernel<<<MROWS, DM>>>(x, enc_w, enc_b);

    for (int i = 0; i < NL; i++) {
        gemm_tf32_cp<<<dim3((2*DI)/64, MROWS/128), 256>>>(
            p_h, in_proj_w + (size_t)i*DM*2*DI, p_xz, MROWS, 2*DI, DM);

        conv_silu_kernel<<<BSZ*256, DI>>>(conv_w + (size_t)i*DI*4, conv_b + (size_t)i*DI);

        gemm_tf32_cp<<<dim3(1, MROWS/128), 256>>>(
            p_u, x_proj_w + (size_t)i*DI*PROJC, p_proj, MROWS, PROJC, DI);

        scan_kernel<<<BSZ*32, 256>>>(A_log + (size_t)i*DI*NST, Dv + (size_t)i*DI,
                                     dt_w + (size_t)i*DTR*DI, dt_b + (size_t)i*DI);

        gemm_tf32_cp<<<dim3(DM/64, MROWS/128), 256>>>(
            p_ymod, out_proj_w + (size_t)i*DI*DM, p_out2, MROWS, DM, DI);

        ln_kernel<<<MROWS, DM>>>(ln_g + (size_t)i*DM, ln_b + (size_t)i*DM);
    }

    pool_kernel<<<BSZ, DM>>>();
    dec_kernel<<<1, 128>>>(dec_w, dec_b, (float*)d_out);
}

// round 7
// speedup vs baseline: 3.7225x; 1.0416x over previous
#include <cuda_runtime.h>
#include <cuda_bf16.h>
#include <math.h>

// ---------------- Problem dims ----------------
#define NL    8
#define BSZ   8
#define LSEQ  1024
#define DM    256
#define DI    512
#define NST   16
#define DTR   16
#define PROJC 48
#define MROWS (BSZ*LSEQ)  // 8192

// ---------------- Device scratch ----------------
__device__ float g_h   [MROWS*DM];
__device__ float g_xz  [MROWS*2*DI];
__device__ float g_u   [MROWS*DI];
__device__ float g_proj[MROWS*PROJC];
__device__ float g_ymod[MROWS*DI];
__device__ float g_out2[MROWS*DM];
__device__ float g_pooled[BSZ*DM];

// ---------------- helpers ----------------
__device__ __forceinline__ void mma_tf32(float& d0, float& d1, float& d2, float& d3,
                                         unsigned a0, unsigned a1, unsigned a2, unsigned a3,
                                         unsigned b0, unsigned b1) {
    asm volatile(
        "mma.sync.aligned.m16n8k8.row.col.f32.tf32.tf32.f32 "
        "{%0,%1,%2,%3}, {%4,%5,%6,%7}, {%8,%9}, {%0,%1,%2,%3};\n"
        : "+f"(d0), "+f"(d1), "+f"(d2), "+f"(d3)
        : "r"(a0), "r"(a1), "r"(a2), "r"(a3), "r"(b0), "r"(b1));
}
__device__ __forceinline__ void cp16(unsigned dst, const void* src) {
    asm volatile("cp.async.cg.shared.global [%0], [%1], 16;\n" :: "r"(dst), "l"(src));
}
__device__ __forceinline__ void cp_commit() { asm volatile("cp.async.commit_group;\n"); }
__device__ __forceinline__ void cp_wait0()  { asm volatile("cp.async.wait_group 0;\n"); }
__device__ __forceinline__ void cp_wait1()  { asm volatile("cp.async.wait_group 1;\n"); }
__device__ __forceinline__ void cp_wait2()  { asm volatile("cp.async.wait_group 2;\n"); }

// ---------------- Encoder ----------------
__global__ void enc_kernel(const float* __restrict__ x,
                           const float* __restrict__ w,
                           const float* __restrict__ bb) {
    int bl = blockIdx.x;
    int m  = threadIdx.x;
    int b = bl >> 10, l = bl & 1023;
    float acc = bb[m];
#pragma unroll
    for (int c = 0; c < 3; c++)
        acc = fmaf(x[(b*3 + c)*LSEQ + l], w[c*DM + m], acc);
    g_h[bl*DM + m] = acc;
}

// ---------------- TF32 GEMM, cp.async 4-stage pipeline ----------------
// Tile BMx64x16, 256 threads (8 warps: 4m x 2n), warp tile (BM/4)x32.
// M%BM==0, K%16==0, N guarded. fp32 bits fed as tf32 (RZ).
#define ASTR 20
#define BSTR 72
template<int BM>
__global__ void __launch_bounds__(256, 2)
gemm_tf32_cp(const float* __restrict__ A,
             const float* __restrict__ B,
             float* __restrict__ C,
             int M, int N, int K) {
    constexpr int AM = BM / 64;            // m16 atoms per warp: 2 (BM=128) or 1 (BM=64)
    __shared__ unsigned As[4][BM*ASTR];
    __shared__ unsigned Bs[4][16*BSTR];

    const int tid  = threadIdx.x;
    const int lane = tid & 31;
    const int wid  = tid >> 5;
    const int wm   = wid & 3;
    const int wn   = wid >> 2;
    const int m0   = blockIdx.y * BM;
    const int n0   = blockIdx.x * 64;
    const int r = lane >> 2;
    const int c = lane & 3;

    if (n0 + 64 > N) {
#pragma unroll
        for (int s = 0; s < 4; s++)
            for (int i = tid; i < 16*BSTR; i += 256)
                Bs[s][i] = 0u;
        __syncthreads();
    }

    const int bRow = tid >> 4;
    const int bNq  = tid & 15;
    const bool bOk = (n0 + bNq*4 + 3) < N;

    unsigned aBase[4], bBase[4];
#pragma unroll
    for (int s = 0; s < 4; s++) {
        aBase[s] = (unsigned)__cvta_generic_to_shared(&As[s][0]);
        bBase[s] = (unsigned)__cvta_generic_to_shared(&Bs[s][0]);
    }

    auto loadTile = [&](int t, int s) {
        int k0 = t * 16;
#pragma unroll
        for (int j = 0; j < AM; j++) {           // BM*4 slots of 16B / 256 threads
            int slot = j*256 + tid;
            int row = slot >> 2, kq = slot & 3;
            cp16(aBase[s] + (row*ASTR + kq*4)*4,
                 A + (size_t)(m0 + row)*K + k0 + kq*4);
        }
        if (bOk)
            cp16(bBase[s] + (bRow*BSTR + bNq*4)*4,
                 B + (size_t)(k0 + bRow)*N + n0 + bNq*4);
        cp_commit();
    };

    float acc[AM][4][4] = {};
    const int T = K >> 4;

    loadTile(0, 0); loadTile(1, 1); loadTile(2, 2);

    for (int t = 0; t < T; t++) {
        int cur = t & 3;
        cp_wait2();
        __syncthreads();
        if (t + 3 < T) loadTile(t + 3, (t + 3) & 3);
        else           cp_commit();              // keep wait_group arithmetic exact

        const unsigned* Ab = As[cur];
        const unsigned* Bb = Bs[cur];
#pragma unroll
        for (int kk = 0; kk < 16; kk += 8) {
            unsigned af[AM][4], bf[4][2];
#pragma unroll
            for (int am = 0; am < AM; am++) {
                int mrow = wm*(BM/4) + am*16;
                af[am][0] = Ab[(mrow + r    )*ASTR + kk + c    ];
                af[am][1] = Ab[(mrow + r + 8)*ASTR + kk + c    ];
                af[am][2] = Ab[(mrow + r    )*ASTR + kk + c + 4];
                af[am][3] = Ab[(mrow + r + 8)*ASTR + kk + c + 4];
            }
#pragma unroll
            for (int bn = 0; bn < 4; bn++) {
                int ncol = wn*32 + bn*8 + r;
                bf[bn][0] = Bb[(kk + c    )*BSTR + ncol];
                bf[bn][1] = Bb[(kk + c + 4)*BSTR + ncol];
            }
#pragma unroll
            for (int am = 0; am < AM; am++)
#pragma unroll
                for (int bn = 0; bn < 4; bn++)
                    mma_tf32(acc[am][bn][0], acc[am][bn][1], acc[am][bn][2], acc[am][bn][3],
                             af[am][0], af[am][1], af[am][2], af[am][3],
                             bf[bn][0], bf[bn][1]);
        }
    }

#pragma unroll
    for (int am = 0; am < AM; am++) {
#pragma unroll
        for (int bn = 0; bn < 4; bn++) {
            int m = m0 + wm*(BM/4) + am*16 + r;
            int n = n0 + wn*32 + bn*8 + 2*c;
            if (n + 1 < N) {
                *(float2*)(C + (size_t)m*N + n)       = make_float2(acc[am][bn][0], acc[am][bn][1]);
                *(float2*)(C + (size_t)(m + 8)*N + n) = make_float2(acc[am][bn][2], acc[am][bn][3]);
            } else if (n < N) {
                C[(size_t)m*N + n]       = acc[am][bn][0];
                C[(size_t)(m + 8)*N + n] = acc[am][bn][2];
            }
        }
    }
}

// ---------------- Causal depthwise conv (K=4) + SiLU ----------------
__global__ void conv_silu_kernel(const float* __restrict__ cw,
                                 const float* __restrict__ cb) {
    int d = threadIdx.x;
    int t = blockIdx.x;
    int b = t >> 8, lt = t & 255;
    int l0 = lt * 4;
    float w0 = cw[d*4+0], w1 = cw[d*4+1], w2 = cw[d*4+2], w3 = cw[d*4+3];
    float bias = cb[d];
    float v[7];
#pragma unroll
    for (int j = 0; j < 7; j++) {
        int ll = l0 - 3 + j;
        v[j] = (ll >= 0) ? g_xz[(size_t)((b << 10) + ll)*(2*DI) + d] : 0.f;
    }
#pragma unroll
    for (int i = 0; i < 4; i++) {
        float acc = bias;
        acc = fmaf(v[i],   w0, acc);
        acc = fmaf(v[i+1], w1, acc);
        acc = fmaf(v[i+2], w2, acc);
        acc = fmaf(v[i+3], w3, acc);
        float s = acc / (1.f + __expf(-acc));
        g_u[(size_t)((b << 10) + l0 + i)*DI + d] = s;
    }
}

// ---------------- Fused dt + selective scan + gate, cp.async staged ----------------
#define SCH 64
#define SPSTR 52
__global__ void __launch_bounds__(256)
scan_kernel(const float* __restrict__ A_log,
            const float* __restrict__ Dv,
            const float* __restrict__ dtw,
            const float* __restrict__ dtb) {
    __shared__ float sp[2][SCH*SPSTR];
    __shared__ float su[2][SCH*16];
    __shared__ float sz[2][SCH*16];
    __shared__ float so[SCH*16];

    const int b  = blockIdx.x >> 5;
    const int d0 = (blockIdx.x & 31) * 16;
    const int tid = threadIdx.x;
    const int hw = tid >> 4;
    const int n  = tid & 15;
    const int d  = d0 + hw;
    const int lane = tid & 31;
    const int hbase = lane & 16;
    const int blbase = b << 10;

    const int rl = tid >> 2;
    const int rq = tid & 3;

    unsigned spB[2], suB[2], szB[2];
#pragma unroll
    for (int s = 0; s < 2; s++) {
        spB[s] = (unsigned)__cvta_generic_to_shared(&sp[s][0]);
        suB[s] = (unsigned)__cvta_generic_to_shared(&su[s][0]);
        szB[s] = (unsigned)__cvta_generic_to_shared(&sz[s][0]);
    }

    auto loadChunk = [&](int c0, int buf) {
        cp16(suB[buf] + (rl*16 + rq*4)*4,
             g_u + (size_t)(blbase + c0 + rl)*DI + d0 + rq*4);
        cp16(szB[buf] + (rl*16 + rq*4)*4,
             g_xz + (size_t)(blbase + c0 + rl)*(2*DI) + DI + d0 + rq*4);
#pragma unroll
        for (int k = 0; k < 3; k++) {
            int s = tid + k*256;
            int l = s / 12, q = s - l*12;
            cp16(spB[buf] + (l*SPSTR + q*4)*4,
                 g_proj + (size_t)(blbase + c0 + l)*PROJC + q*4);
        }
        cp_commit();
    };

    float wdt[DTR];
#pragma unroll
    for (int r = 0; r < DTR; r++) wdt[r] = dtw[r*DI + d];
    const float dtbv = dtb[d];
    const float Ad = -__expf(A_log[d*NST + n]);
    const float Dd = Dv[d];
    float state = 0.f;

    loadChunk(0, 0);

    for (int cc = 0; cc < LSEQ/SCH; cc++) {
        int buf = cc & 1;
        if (cc + 1 < LSEQ/SCH) { loadChunk((cc+1)*SCH, buf ^ 1); cp_wait1(); }
        else                   { cp_wait0(); }
        __syncthreads();

        const float* P = sp[buf];
        const float* U = su[buf];
        const float* Z = sz[buf];

        float dtv4[4];
#pragma unroll
        for (int j = 0; j < 4; j++) {
            float a = dtbv;
            const float* row = &P[(j*16 + n)*SPSTR];
#pragma unroll
            for (int r = 0; r < DTR; r++) a = fmaf(row[r], wdt[r], a);
            dtv4[j] = (a > 20.f) ? a : log1pf(__expf(a));
        }

#pragma unroll 4
        for (int l = 0; l < SCH; l++) {
            float dtv = __shfl_sync(0xffffffffu, dtv4[l >> 4], hbase + (l & 15), 32);
            float uv = U[l*16 + hw];
            float Bv = P[l*SPSTR + DTR + n];
            float Cv = P[l*SPSTR + DTR + NST + n];
            state = fmaf(__expf(dtv*Ad), state, dtv*uv*Bv);
            float p = state * Cv;
            p += __shfl_xor_sync(0xffffffffu, p, 8);
            p += __shfl_xor_sync(0xffffffffu, p, 4);
            p += __shfl_xor_sync(0xffffffffu, p, 2);
            p += __shfl_xor_sync(0xffffffffu, p, 1);
            if (n == 0) {
                float zv = Z[l*16 + hw];
                float sz_ = zv / (1.f + __expf(-zv));
                so[l*16 + hw] = (p + uv*Dd) * sz_;
            }
        }
        __syncthreads();

        {
            float4 v = *(const float4*)&so[rl*16 + rq*4];
            *(float4*)(g_ymod + (size_t)(blbase + cc*SCH + rl)*DI + d0 + rq*4) = v;
        }
    }
}

// ---------------- Residual add + LayerNorm ----------------
__global__ void ln_kernel(const float* __restrict__ gamma,
                          const float* __restrict__ beta) {
    __shared__ float s1[8], s2[8];
    int bl = blockIdx.x;
    int m  = threadIdx.x;
    float t = g_out2[bl*DM + m] + g_h[bl*DM + m];
    float v1 = t, v2 = t*t;
#pragma unroll
    for (int o = 16; o > 0; o >>= 1) {
        v1 += __shfl_xor_sync(0xffffffffu, v1, o);
        v2 += __shfl_xor_sync(0xffffffffu, v2, o);
    }
    if ((m & 31) == 0) { s1[m >> 5] = v1; s2[m >> 5] = v2; }
    __syncthreads();
    float sum = 0.f, sq = 0.f;
#pragma unroll
    for (int i = 0; i < 8; i++) { sum += s1[i]; sq += s2[i]; }
    float mean = sum * (1.f/DM);
    float var  = sq * (1.f/DM) - mean*mean;
    float rs = rsqrtf(var + 1e-5f);
    g_h[bl*DM + m] = (t - mean) * rs * gamma[m] + beta[m];
}

// ---------------- Mean pool ----------------
__global__ void pool_kernel() {
    int b = blockIdx.x;
    int m = threadIdx.x;
    float s = 0.f;
    for (int l = 0; l < LSEQ; l++)
        s += g_h[(size_t)((b << 10) + l)*DM + m];
    g_pooled[b*DM + m] = s * (1.f/LSEQ);
}

// ---------------- Decoder ----------------
__global__ void dec_kernel(const float* __restrict__ w,
                           const float* __restrict__ bb,
                           float* __restrict__ out) {
    int i = threadIdx.x;
    if (i < BSZ*10) {
        int b = i / 10, o = i % 10;
        float acc = bb[o];
#pragma unroll 8
        for (int m = 0; m < DM; m++)
            acc = fmaf(g_pooled[b*DM + m], w[m*10 + o], acc);
        out[i] = acc;
    }
}

// ---------------- Launch ----------------
extern "C" void kernel_launch(void* const* d_in, const int* in_sizes, int n_in,
                              void* d_out, int out_size) {
    const float* x         = (const float*)d_in[0];
    const float* enc_w     = (const float*)d_in[1];
    const float* enc_b     = (const float*)d_in[2];
    const float* in_proj_w = (const float*)d_in[3];
    const float* conv_w    = (const float*)d_in[4];
    const float* conv_b    = (const float*)d_in[5];
    const float* x_proj_w  = (const float*)d_in[6];
    const float* dt_w      = (const float*)d_in[7];
    const float* dt_b      = (const float*)d_in[8];
    const float* A_log     = (const float*)d_in[9];
    const float* Dv        = (const float*)d_in[10];
    const float* out_proj_w= (const float*)d_in[11];
    const float* ln_g      = (const float*)d_in[12];
    const float* ln_b      = (const float*)d_in[13];
    const float* dec_w     = (const float*)d_in[14];
    const float* dec_b     = (const float*)d_in[15];

    float *p_h, *p_xz, *p_u, *p_proj, *p_ymod, *p_out2;
    cudaGetSymbolAddress((void**)&p_h,    g_h);
    cudaGetSymbolAddress((void**)&p_xz,   g_xz);
    cudaGetSymbolAddress((void**)&p_u,    g_u);
    cudaGetSymbolAddress((void**)&p_proj, g_proj);
    cudaGetSymbolAddress((void**)&p_ymod, g_ymod);
    cudaGetSymbolAddress((void**)&p_out2, g_out2);

    enc_kernel<<<MROWS, DM>>>(x, enc_w, enc_b);

    for (int i = 0; i < NL; i++) {
        // xz = h @ in_proj_w[i]   (8192x256 @ 256x1024)
        gemm_tf32_cp<128><<<dim3((2*DI)/64, MROWS/128), 256>>>(
            p_h, in_proj_w + (size_t)i*DM*2*DI, p_xz, MROWS, 2*DI, DM);

        conv_silu_kernel<<<BSZ*256, DI>>>(conv_w + (size_t)i*DI*4, conv_b + (size_t)i*DI);

        // proj = u @ x_proj_w[i]  (8192x512 @ 512x48) — BM=64 for SM coverage
        gemm_tf32_cp<64><<<dim3(1, MROWS/64), 256>>>(
            p_u, x_proj_w + (size_t)i*DI*PROJC, p_proj, MROWS, PROJC, DI);

        scan_kernel<<<BSZ*32, 256>>>(A_log + (size_t)i*DI*NST, Dv + (size_t)i*DI,
                                     dt_w + (size_t)i*DTR*DI, dt_b + (size_t)i*DI);

        // out2 = ymod @ out_proj_w[i]  (8192x512 @ 512x256)
        gemm_tf32_cp<128><<<dim3(DM/64, MROWS/128), 256>>>(
            p_ymod, out_proj_w + (size_t)i*DI*DM, p_out2, MROWS, DM, DI);

        ln_kernel<<<MROWS, DM>>>(ln_g + (size_t)i*DM, ln_b + (size_t)i*DM);
    }

    pool_kernel<<<BSZ, DM>>>();
    dec_kernel<<<1, 128>>>(dec_w, dec_b, (float*)d_out);
}